// round 8
// baseline (speedup 1.0000x reference)
#include <cuda_runtime.h>
#include <math.h>

typedef unsigned long long ull;

#define D        64
#define KCODES   1024
#define KC       128         // codes per chunk
#define MT       64          // rows (vectors) per block
#define NTHREADS 256
#define W2       132         // dup-x tile row width (floats): 128 data + 4 pad; 132%4==0 -> 16B-aligned rows
#define W3       130         // code tile row width (floats): 128 data + 2 pad; 8B-aligned rows

// scratch (no cudaMalloc allowed)
__device__ int   g_counts[KCODES];
__device__ float g_loss[2];   // [0] = sum (qst-x)^2, [1] = sum (q-x)^2
__device__ unsigned g_done;

__device__ __forceinline__ ull pack2(float lo, float hi) {
    ull r;
    asm("mov.b64 %0, {%1, %2};" : "=l"(r) : "f"(lo), "f"(hi));
    return r;
}
__device__ __forceinline__ ull fma2(ull a, ull b, ull c) {
    ull d;
    asm("fma.rn.f32x2 %0, %1, %2, %3;" : "=l"(d) : "l"(a), "l"(b), "l"(c));
    return d;
}
__device__ __forceinline__ float lo32(ull v) { return __uint_as_float((unsigned)(v & 0xffffffffull)); }
__device__ __forceinline__ float hi32(ull v) { return __uint_as_float((unsigned)(v >> 32)); }

// ---------------------------------------------------------------------------
// fused: distance GEMM + argmin + quantize(ST) + losses + counts + finalize.
// 256 threads, 64 rows/block, 2 blocks/SM (regs<=128 via launch_bounds).
// thread micro-tile: 4 rows x 8 codes -> 16 packed f32x2 FMA per d-iter vs
// 6 conflict-free crossbar wavefronts (2x LDS.128 dup-x + 4x LDS.64 codes).
// 16 warps/SM hide LDS latency; FMA pipe is the intended binder.
// ---------------------------------------------------------------------------
__global__ void __launch_bounds__(NTHREADS, 2)
vq_fused(const float* __restrict__ xin, const float* __restrict__ cb,
         float* __restrict__ outq, float* __restrict__ outt,
         float* __restrict__ outs, float inv_ND, float invN) {
    extern __shared__ float smem[];
    float* sx2 = smem;               // [D][W2] dup-stored x tile (d-major)
    float* sc  = smem + D * W2;      // [D][W3] code chunk, natural (d-major)
    float* scn = smem + D * W2 + D * W3;  // [KC] code norms of chunk
    __shared__ int s_last;

    const int tid  = threadIdx.x;
    const int lane = tid & 31;
    const int warp = tid >> 5;
    const int hl   = lane & 15;              // colgrp: 8 codes {2*(j*16+hl)+0/1}
    const int half = lane >> 4;
    const int rowgrp = (warp << 1) | half;   // 0..15 -> 4 rows each
    const int rb = rowgrp * 4;               // local row base
    const int row0 = blockIdx.x * MT;

    // ---- load x tile, duplicate-stored transposed (coalesced global read) ----
    #pragma unroll
    for (int t = 0; t < (MT * D) / NTHREADS; t++) {
        int lin = t * NTHREADS + tid;
        int r = lin >> 6;
        int d = lin & 63;
        float v = xin[(size_t)row0 * D + lin];
        *(ull*)&sx2[d * W2 + 2 * r] = pack2(v, v);
    }
    __syncthreads();

    // ---- |x|^2 for my 4 rows (16-lane cooperative over d) ----
    float xn[4];
    #pragma unroll
    for (int i = 0; i < 4; i++) {
        int r = rb + i;
        float a0 = sx2[(hl)      * W2 + 2 * r];
        float a1 = sx2[(hl + 16) * W2 + 2 * r];
        float a2 = sx2[(hl + 32) * W2 + 2 * r];
        float a3 = sx2[(hl + 48) * W2 + 2 * r];
        float s = a0 * a0 + a1 * a1 + a2 * a2 + a3 * a3;
        s += __shfl_xor_sync(0xffffffffu, s, 8);
        s += __shfl_xor_sync(0xffffffffu, s, 4);
        s += __shfl_xor_sync(0xffffffffu, s, 2);
        s += __shfl_xor_sync(0xffffffffu, s, 1);
        xn[i] = s;
    }

    float bd[4];
    int   bi[4];
    #pragma unroll
    for (int i = 0; i < 4; i++) { bd[i] = 3.4e38f; bi[i] = 0; }

    // ---- chunk loop over codebook ----
    for (int ck = 0; ck < KCODES / KC; ck++) {
        const int kbase = ck * KC;
        __syncthreads();
        #pragma unroll
        for (int t = 0; t < (KC * D) / NTHREADS; t++) {
            int lin = t * NTHREADS + tid;
            int kc = lin >> 6;
            int d  = lin & 63;
            sc[d * W3 + kc] = cb[(size_t)(kbase + kc) * D + d];
        }
        // per-chunk code norms (cheap, hits L1/L2)
        if (tid < KC) {
            const float* c = cb + (size_t)(kbase + tid) * D;
            float s = 0.f;
            #pragma unroll
            for (int q = 0; q < D / 4; q++) {
                float4 v = *(const float4*)(c + 4 * q);
                s = fmaf(v.x, v.x, fmaf(v.y, v.y, fmaf(v.z, v.z, fmaf(v.w, v.w, s))));
            }
            scn[tid] = s;
        }
        __syncthreads();

        ull acc[4][4];
        #pragma unroll
        for (int r = 0; r < 4; r++)
            #pragma unroll
            for (int j = 0; j < 4; j++) acc[r][j] = 0ull;

        #pragma unroll 4
        for (int d = 0; d < D; d++) {
            const float* xrow = &sx2[d * W2 + 2 * rb];     // 4 dup'd rows = 8 floats, 16B-aligned
            ulonglong2 xA = *(const ulonglong2*)(xrow);     // {x0,x0},{x1,x1}
            ulonglong2 xB = *(const ulonglong2*)(xrow + 4); // {x2,x2},{x3,x3}
            const float* crow = &sc[d * W3 + 2 * hl];
            ull c0 = *(const ull*)(crow);        // codes {2hl, 2hl+1}  (lanes 8B stride: conflict-free)
            ull c1 = *(const ull*)(crow + 32);   // +16 codes
            ull c2 = *(const ull*)(crow + 64);
            ull c3 = *(const ull*)(crow + 96);
            acc[0][0] = fma2(xA.x, c0, acc[0][0]);
            acc[0][1] = fma2(xA.x, c1, acc[0][1]);
            acc[0][2] = fma2(xA.x, c2, acc[0][2]);
            acc[0][3] = fma2(xA.x, c3, acc[0][3]);
            acc[1][0] = fma2(xA.y, c0, acc[1][0]);
            acc[1][1] = fma2(xA.y, c1, acc[1][1]);
            acc[1][2] = fma2(xA.y, c2, acc[1][2]);
            acc[1][3] = fma2(xA.y, c3, acc[1][3]);
            acc[2][0] = fma2(xB.x, c0, acc[2][0]);
            acc[2][1] = fma2(xB.x, c1, acc[2][1]);
            acc[2][2] = fma2(xB.x, c2, acc[2][2]);
            acc[2][3] = fma2(xB.x, c3, acc[2][3]);
            acc[3][0] = fma2(xB.y, c0, acc[3][0]);
            acc[3][1] = fma2(xB.y, c1, acc[3][1]);
            acc[3][2] = fma2(xB.y, c2, acc[3][2]);
            acc[3][3] = fma2(xB.y, c3, acc[3][3]);
        }

        // distances (reference add order) + running argmin.
        // per-thread visit order is k-ascending (j asc, lo=2k before hi=2k+1);
        // strict < keeps the lowest index.
        #pragma unroll
        for (int j = 0; j < 4; j++) {
            int   kp  = 2 * (j * 16 + hl);       // local lo code index
            int   k0  = kbase + kp;
            float cn0 = scn[kp];
            float cn1 = scn[kp + 1];
            #pragma unroll
            for (int r = 0; r < 4; r++) {
                float s0 = lo32(acc[r][j]);
                float s1 = hi32(acc[r][j]);
                float d0 = (xn[r] + cn0) - 2.f * s0;
                float d1 = (xn[r] + cn1) - 2.f * s1;
                if (d0 < bd[r]) { bd[r] = d0; bi[r] = k0; }
                if (d1 < bd[r]) { bd[r] = d1; bi[r] = k0 + 1; }
            }
        }
    }

    // ---- argmin reduce across the 16 colgrp lanes (tie -> lower index) ----
    #pragma unroll
    for (int i = 0; i < 4; i++) {
        float d = bd[i];
        int   b = bi[i];
        #pragma unroll
        for (int off = 8; off >= 1; off >>= 1) {
            float od = __shfl_xor_sync(0xffffffffu, d, off);
            int   ob = __shfl_xor_sync(0xffffffffu, b, off);
            if (od < d || (od == d && ob < b)) { d = od; b = ob; }
        }
        bd[i] = d;
        bi[i] = b;
    }

    // ---- epilogue: tokens, quantized_st, loss & usage partials ----
    float e_acc = 0.f, q_acc = 0.f;
    #pragma unroll
    for (int i = 0; i < 4; i++) {
        int row = row0 + rb + i;
        int b   = bi[i];
        if (hl == 0) {
            outt[row] = (float)b;
            atomicAdd(&g_counts[b], 1);
        }
        float4 q4 = *(const float4*)&cb[(size_t)b * D + hl * 4];
        float4 x4 = *(const float4*)&xin[(size_t)row * D + hl * 4];
        float t0 = q4.x - x4.x, t1 = q4.y - x4.y, t2 = q4.z - x4.z, t3 = q4.w - x4.w;
        float4 o;
        o.x = x4.x + t0; o.y = x4.y + t1; o.z = x4.z + t2; o.w = x4.w + t3;
        *(float4*)&outq[(size_t)row * D + hl * 4] = o;
        float e0 = o.x - x4.x, e1 = o.y - x4.y, e2 = o.z - x4.z, e3 = o.w - x4.w;
        e_acc += e0 * e0 + e1 * e1 + e2 * e2 + e3 * e3;
        q_acc += t0 * t0 + t1 * t1 + t2 * t2 + t3 * t3;
    }
    #pragma unroll
    for (int off = 16; off >= 1; off >>= 1) {
        e_acc += __shfl_xor_sync(0xffffffffu, e_acc, off);
        q_acc += __shfl_xor_sync(0xffffffffu, q_acc, off);
    }
    if (lane == 0) {
        atomicAdd(&g_loss[0], e_acc);
        atomicAdd(&g_loss[1], q_acc);
    }

    // ---- last-block finalize (4 scalars) + scratch reset for next replay ----
    __threadfence();
    __syncthreads();
    if (tid == 0) {
        unsigned t = atomicAdd(&g_done, 1u);
        s_last = (t == gridDim.x - 1) ? 1 : 0;
    }
    __syncthreads();
    if (s_last) {
        float h = 0.f;
        for (int k = tid; k < KCODES; k += NTHREADS) {
            float p = (float)g_counts[k] * invN;
            h += p * logf(p + 1e-10f);
        }
        sx2[tid] = h;
        __syncthreads();
        for (int s = NTHREADS / 2; s > 0; s >>= 1) {
            if (tid < s) sx2[tid] += sx2[tid + s];
            __syncthreads();
        }
        if (tid == 0) {
            float Le = g_loss[0] * inv_ND;
            float Lq = g_loss[1] * inv_ND;
            float commitment = 0.25f * Le;       // COMMITMENT_COST
            outs[0] = commitment + Lq;           // vq_loss
            outs[1] = commitment;                // commitment_loss
            outs[2] = Lq;                        // codebook_loss
            outs[3] = expf(-sx2[0]);             // perplexity
            g_loss[0] = 0.f;
            g_loss[1] = 0.f;
            g_done = 0u;
        }
        __syncthreads();
        for (int k = tid; k < KCODES; k += NTHREADS) g_counts[k] = 0;
    }
}

extern "C" void kernel_launch(void* const* d_in, const int* in_sizes, int n_in,
                              void* d_out, int out_size) {
    const float* x  = (const float*)d_in[0];
    const float* cb = (const float*)d_in[1];
    float* out = (float*)d_out;

    const int ND = in_sizes[0];       // N * D
    const int N  = ND / D;            // 262144

    float* outq = out;                // quantized_st, ND floats
    float* outt = out + ND;           // tokens (as float), N floats
    float* outs = out + ND + N;       // 4 scalars

    const int smem_bytes = (D * W2 + D * W3 + KC) * (int)sizeof(float);  // ~67.6 KB
    cudaFuncSetAttribute(vq_fused, cudaFuncAttributeMaxDynamicSharedMemorySize, smem_bytes);

    vq_fused<<<N / MT, NTHREADS, smem_bytes>>>(x, cb, outq, outt, outs,
                                               1.f / (float)ND, 1.f / (float)N);
}